// round 14
// baseline (speedup 1.0000x reference)
#include <cuda_runtime.h>
#include <cstdint>
#include <cstddef>

// ============================================================================
// Problem constants
// ============================================================================
static constexpr int BATCH  = 16384;
static constexpr int IN_DIM = 512;
static constexpr int UNITS  = 256;
static constexpr int NEXP   = 8;
static constexpr int NTASK  = 4;
static constexpr int NCOL   = UNITS * NEXP;   // 2048, n = u*8+e
static constexpr int GCOL   = NEXP * NTASK;   // 32,   g = e*4+t

// Fragment-block geometry (mma.m16n8k8)
static constexpr int MBLKS  = BATCH / 16;     // 1024
static constexpr int KBLKS  = IN_DIM / 8;     // 64
static constexpr int KBLK2S = IN_DIM / 16;    // 32
static constexpr int NBLKS  = NCOL / 8;       // 256
static constexpr int GNBLKS = GCOL / 8;       // 4

// Tiling: 4 warps of 64x64
static constexpr int BM     = 128;            // 8 m_blks -> 2048 CTAs
static constexpr int BN     = 128;            // 16 n_blks
static constexpr int KC     = 32;             // 4 k_blks / 2 k_blk2s
static constexpr int KSTEPS = IN_DIM / KC;    // 16
static constexpr int STAGES = 3;
static constexpr int NTHREADS = 128;          // 4 warps, 2(m) x 2(n), warp tile 64x64

// Shared memory (float4 units): stage = A(8*4*32) + B(16*2*32) = 2048 f4 = 32KB
static constexpr int A_STAGE_F4 = 8 * 4 * 32;     // 1024
static constexpr int B_STAGE_F4 = 16 * 2 * 32;    // 1024
static constexpr int STAGE_F4   = A_STAGE_F4 + B_STAGE_F4;  // 2048
static constexpr int HDR_F4     = 32;             // be slice (128 floats)
static constexpr int SMEM_F4    = HDR_F4 + STAGES * STAGE_F4;
static constexpr int SMEM_BYTES = SMEM_F4 * 16;   // 98816 (x2 CTA = 193 KB)
static constexpr int C_LD       = BN + 4;         // 132 (staging 128*132*4 = 67.6 KB)

// ============================================================================
// Device scratch (no allocations allowed)
// ============================================================================
__device__ float  g_gates[BATCH * GCOL];                  // softmaxed gates [b][e*4+t]
__device__ float4 g_xA  [(size_t)MBLKS * KBLKS * 32];     // A fragments (32 MB)
__device__ float4 g_WeB [(size_t)NBLKS * KBLK2S * 32];    // We B fragments (4 MB)
__device__ float4 g_WgB [(size_t)GNBLKS * KBLK2S * 32];   // Wg B fragments (64 KB)

// ============================================================================
// Helpers
// ============================================================================
__device__ __forceinline__ uint32_t smem_u32(const void* p) {
    uint32_t a;
    asm("{ .reg .u64 t; cvta.to.shared.u64 t, %1; cvt.u32.u64 %0, t; }" : "=r"(a) : "l"(p));
    return a;
}
__device__ __forceinline__ float tf32_rn(float f) {
    uint32_t o; asm("cvt.rn.tf32.f32 %0, %1;" : "=r"(o) : "f"(f));
    return __uint_as_float(o);
}
__device__ __forceinline__ void cp_async16(uint32_t dst, const void* src) {
    asm volatile("cp.async.cg.shared.global [%0], [%1], 16;\n" :: "r"(dst), "l"(src));
}
#define CP_COMMIT()       asm volatile("cp.async.commit_group;\n" ::: "memory")
#define CP_WAIT_GROUP_1() asm volatile("cp.async.wait_group 1;\n" ::: "memory")

// D += A(16x8) * B(8x8), tf32 operands, f32 accum
__device__ __forceinline__ void mma_tf32(float* c, const float4& a, float b0, float b1) {
    asm volatile(
        "mma.sync.aligned.m16n8k8.row.col.f32.tf32.tf32.f32 "
        "{%0,%1,%2,%3}, {%4,%5,%6,%7}, {%8,%9}, {%0,%1,%2,%3};"
        : "+f"(c[0]), "+f"(c[1]), "+f"(c[2]), "+f"(c[3])
        : "r"(__float_as_uint(a.x)), "r"(__float_as_uint(a.y)),
          "r"(__float_as_uint(a.z)), "r"(__float_as_uint(a.w)),
          "r"(__float_as_uint(b0)),  "r"(__float_as_uint(b1)));
}

// ============================================================================
// prep Wg: tiny kernel packing Wg into B-fragment order (4096 f4 slots)
// ============================================================================
__global__ void __launch_bounds__(128)
prep_Wg_kernel(const float* __restrict__ Wg) {
    int slot = blockIdx.x * 128 + threadIdx.x;   // 32 blocks x 128 = 4096
    int gn   = slot >> 10;
    int rem  = slot & 1023;
    int k2   = rem >> 5;
    int lane = rem & 31;
    int gr = lane >> 2, tig = lane & 3;
    int n  = gn * 8 + gr;
    int kb = k2 * 16;
    float4 v;
    v.x = tf32_rn(__ldg(Wg + (size_t)(kb + tig)      * GCOL + n));
    v.y = tf32_rn(__ldg(Wg + (size_t)(kb + tig + 4)  * GCOL + n));
    v.z = tf32_rn(__ldg(Wg + (size_t)(kb + 8 + tig)  * GCOL + n));
    v.w = tf32_rn(__ldg(Wg + (size_t)(kb + 12 + tig) * GCOL + n));
    g_WgB[slot] = v;
}

// ============================================================================
// Gate kernel: x tf32-round + A-fragment pack + tensor-core gate logits +
// softmax. ALSO packs a uniform 256-slot slice of We B-fragments per block
// (1024 blocks x 256 = 262144 slots = full g_WeB), replacing prep_We.
// ============================================================================
static constexpr int XS_LD = IN_DIM + 4;   // 516 (conflict-free pack reads)

__global__ void __launch_bounds__(512)
gate_kernel(const float4* __restrict__ x4, const float* __restrict__ bg,
            const float* __restrict__ We) {
    __shared__ float xs[16][XS_LD];        // 33 KB
    __shared__ float ls[16][GCOL];         //  2 KB
    const int tid  = threadIdx.x;
    const int wid  = tid >> 5;
    const int lane = tid & 31;
    const int gr   = lane >> 2, tig = lane & 3;
    const int blk  = blockIdx.x;           // m_blk
    const int b0   = blk * 16;

    // Uniform We B-fragment pack slice: 256 slots for this block.
    // g_WeB flat index == global slot id (n_blk*1024 + k2*32 + lane).
    if (tid < 256) {
        int s = blk * 256 + tid;
        int rem  = s & 1023;
        int k2   = rem >> 5;
        int ln   = rem & 31;
        int g2 = ln >> 2, t2 = ln & 3;
        int n  = (s >> 10) * 8 + g2;
        int kb = k2 * 16;
        float4 v;
        v.x = tf32_rn(__ldg(We + (size_t)(kb + t2)      * NCOL + n));
        v.y = tf32_rn(__ldg(We + (size_t)(kb + t2 + 4)  * NCOL + n));
        v.z = tf32_rn(__ldg(We + (size_t)(kb + 8 + t2)  * NCOL + n));
        v.w = tf32_rn(__ldg(We + (size_t)(kb + 12 + t2) * NCOL + n));
        g_WeB[s] = v;
    }

    // load + tf32-round x tile into smem
    #pragma unroll
    for (int i = 0; i < 4; i++) {
        int idx = tid + i * 512;           // float4 index within 16x512 tile
        int rr = idx >> 7, c = idx & 127;
        float4 v = x4[(size_t)(b0 + rr) * (IN_DIM / 4) + c];
        v.x = tf32_rn(v.x); v.y = tf32_rn(v.y); v.z = tf32_rn(v.z); v.w = tf32_rn(v.w);
        *(float4*)&xs[rr][c * 4] = v;
    }
    __syncthreads();

    // write A fragments to gmem (2048 slots = 64 k_blk x 32 lanes)
    #pragma unroll
    for (int i = 0; i < 4; i++) {
        int slot = tid + i * 512;
        int k_blk = slot >> 5;
        int ln    = slot & 31;
        int g2 = ln >> 2, t2 = ln & 3;
        int kc = k_blk * 8;
        float4 v;
        v.x = xs[g2][kc + t2];
        v.y = xs[g2 + 8][kc + t2];
        v.z = xs[g2][kc + t2 + 4];
        v.w = xs[g2 + 8][kc + t2 + 4];
        g_xA[((size_t)blk * KBLKS + k_blk) * 32 + ln] = v;
    }
    __syncthreads();   // own-block global writes now visible to this block

    // gate logits via tensor cores: warps 0..3, one gate n-blk each
    if (wid < GNBLKS) {
        float a[4] = {0.f, 0.f, 0.f, 0.f};
        const float4* WgB = g_WgB + (size_t)wid * KBLK2S * 32;
        const float4* xA  = g_xA + (size_t)blk * KBLKS * 32;
        #pragma unroll 4
        for (int k2 = 0; k2 < KBLK2S; k2++) {
            float4 Bv  = WgB[k2 * 32 + lane];
            float4 Av0 = xA[(k2 * 2) * 32 + lane];
            float4 Av1 = xA[(k2 * 2 + 1) * 32 + lane];
            mma_tf32(a, Av0, Bv.x, Bv.y);
            mma_tf32(a, Av1, Bv.z, Bv.w);
        }
        ls[gr][wid * 8 + 2 * tig]         = a[0];
        ls[gr][wid * 8 + 2 * tig + 1]     = a[1];
        ls[gr + 8][wid * 8 + 2 * tig]     = a[2];
        ls[gr + 8][wid * 8 + 2 * tig + 1] = a[3];
    }
    __syncthreads();

    // softmax over experts, per (row, task)
    if (tid < 64) {
        const int rr = tid >> 2, t = tid & 3;
        float v[NEXP], m = -3.4e38f;
        #pragma unroll
        for (int e = 0; e < NEXP; e++) {
            v[e] = ls[rr][e * 4 + t] + bg[e * 4 + t];
            m = fmaxf(m, v[e]);
        }
        float den = 0.f;
        #pragma unroll
        for (int e = 0; e < NEXP; e++) { v[e] = expf(v[e] - m); den += v[e]; }
        const float inv = 1.f / den;
        #pragma unroll
        for (int e = 0; e < NEXP; e++)
            g_gates[(size_t)(b0 + rr) * GCOL + e * 4 + t] = v[e] * inv;
    }
}

// ============================================================================
// Main kernel: mma.m16n8k8 tf32, 64x64 warp tiles (unchanged from r13 best)
// ============================================================================
__global__ void __launch_bounds__(NTHREADS, 2)
moe_mma_kernel(const float* __restrict__ be, float* __restrict__ out) {
    extern __shared__ float4 smem4[];
    float*  sbe    = (float*)smem4;
    float4* stage0 = smem4 + HDR_F4;

    const int tid  = threadIdx.x;
    const int wid  = tid >> 5;
    const int lane = tid & 31;
    const int gr   = lane >> 2, tig = lane & 3;
    const int warp_m = wid >> 1;        // 0..1 -> rows warp_m*64
    const int warp_n = wid & 1;         // 0..1 -> cols warp_n*64

    const int n_tile = blockIdx.x & 15;
    const int b_tile = blockIdx.x >> 4;
    const int b0  = b_tile * BM;
    const int mb0 = b_tile * 8;         // global m_blk base
    const int nb0 = n_tile * 16;        // global n_blk base

    if (tid < BN) sbe[tid] = be[n_tile * BN + tid];

    float acc[4][8][4];                 // [mi][ni][frag] = 128 regs
    #pragma unroll
    for (int mi = 0; mi < 4; mi++)
        #pragma unroll
        for (int ni = 0; ni < 8; ni++)
            #pragma unroll
            for (int q = 0; q < 4; q++) acc[mi][ni][q] = 0.f;

    auto load_stage = [&](int slot, int kt) {
        float4* As = stage0 + slot * STAGE_F4;
        float4* Bs = As + A_STAGE_F4;
        const uint32_t aB = smem_u32(As);
        const uint32_t bB = smem_u32(Bs);
        // A: 1024 chunks -> 8 per thread
        #pragma unroll
        for (int i = 0; i < 8; i++) {
            int c = tid + i * 128;
            int mb = c >> 7, rem = c & 127;
            size_t g = ((size_t)(mb0 + mb) * KBLKS + (kt * 4 + (rem >> 5))) * 32 + (rem & 31);
            cp_async16(aB + (uint32_t)c * 16, g_xA + g);
        }
        // B: 1024 chunks -> 8 per thread
        #pragma unroll
        for (int i = 0; i < 8; i++) {
            int c = tid + i * 128;
            int nb = c >> 6, rem = c & 63;
            size_t g = ((size_t)(nb0 + nb) * KBLK2S + (kt * 2 + (rem >> 5))) * 32 + (rem & 31);
            cp_async16(bB + (uint32_t)c * 16, g_WeB + g);
        }
    };

    auto compute_stage = [&](int slot) {
        const float4* As = stage0 + slot * STAGE_F4;
        const float4* Bs = As + A_STAGE_F4;
        #pragma unroll
        for (int k2 = 0; k2 < 2; k2++) {
            float4 Bv[8];
            #pragma unroll
            for (int ni = 0; ni < 8; ni++)
                Bv[ni] = Bs[((warp_n * 8 + ni) * 2 + k2) * 32 + lane];
            #pragma unroll
            for (int half = 0; half < 2; half++) {
                const int ks = k2 * 2 + half;
                float4 Av[4];
                #pragma unroll
                for (int mi = 0; mi < 4; mi++)
                    Av[mi] = As[((warp_m * 4 + mi) * 4 + ks) * 32 + lane];
                #pragma unroll
                for (int mi = 0; mi < 4; mi++)
                    #pragma unroll
                    for (int ni = 0; ni < 8; ni++) {
                        if (half == 0) mma_tf32(acc[mi][ni], Av[mi], Bv[ni].x, Bv[ni].y);
                        else           mma_tf32(acc[mi][ni], Av[mi], Bv[ni].z, Bv[ni].w);
                    }
            }
        }
    };

    // Prologue: fill 2 of 3 stages
    load_stage(0, 0); CP_COMMIT();
    load_stage(1, 1); CP_COMMIT();

    // Main loop
    for (int kt = 0; kt < KSTEPS; kt++) {
        CP_WAIT_GROUP_1();
        __syncthreads();
        const int next = kt + 2;
        if (next < KSTEPS) load_stage(next % STAGES, next);
        CP_COMMIT();
        compute_stage(kt % STAGES);
    }

    // ------------------------------------------------------------------
    // Epilogue: stage C through smem, then bias+ReLU+gate combine
    // ------------------------------------------------------------------
    __syncthreads();
    float* Cs = (float*)stage0;   // 128 x 132 floats = 67.6 KB
    #pragma unroll
    for (int mi = 0; mi < 4; mi++) {
        #pragma unroll
        for (int ni = 0; ni < 8; ni++) {
            int row = warp_m * 64 + mi * 16 + gr;
            int col = warp_n * 64 + ni * 8 + 2 * tig;
            *(float2*)&Cs[row * C_LD + col]       = make_float2(acc[mi][ni][0], acc[mi][ni][1]);
            *(float2*)&Cs[(row + 8) * C_LD + col] = make_float2(acc[mi][ni][2], acc[mi][ni][3]);
        }
    }
    __syncthreads();

    const int r = tid;            // row in tile (0..127), one row per thread
    const int b = b0 + r;

    float gate[GCOL];
    {
        const float4* gp = (const float4*)(g_gates + (size_t)b * GCOL);
        #pragma unroll
        for (int q = 0; q < 8; q++) ((float4*)gate)[q] = gp[q];
    }

    float accu[16][NTASK];
    #pragma unroll
    for (int u = 0; u < 16; u++)
        #pragma unroll
        for (int t = 0; t < NTASK; t++) accu[u][t] = 0.f;

    #pragma unroll
    for (int u = 0; u < 16; u++) {
        const int nl = u * 8;
        #pragma unroll
        for (int e = 0; e < NEXP; e++) {
            float v = Cs[r * C_LD + nl + e] + sbe[nl + e];
            v = fmaxf(v, 0.f);
            #pragma unroll
            for (int t = 0; t < NTASK; t++) accu[u][t] += v * gate[e * 4 + t];
        }
    }

    float* ob = out + (size_t)b * UNITS + n_tile * 16;
    #pragma unroll
    for (int t = 0; t < NTASK; t++) {
        #pragma unroll
        for (int q = 0; q < 4; q++) {
            float4 o = make_float4(accu[q * 4 + 0][t], accu[q * 4 + 1][t],
                                   accu[q * 4 + 2][t], accu[q * 4 + 3][t]);
            *(float4*)(ob + (size_t)t * BATCH * UNITS + q * 4) = o;
        }
    }
}

// ============================================================================
// Launch
// ============================================================================
extern "C" void kernel_launch(void* const* d_in, const int* in_sizes, int n_in,
                              void* d_out, int out_size) {
    const float* x  = (const float*)d_in[0];
    const float* We = (const float*)d_in[1];
    const float* be = (const float*)d_in[2];
    const float* Wg = (const float*)d_in[3];
    const float* bg = (const float*)d_in[4];
    float* out = (float*)d_out;

    cudaFuncSetAttribute(moe_mma_kernel, cudaFuncAttributeMaxDynamicSharedMemorySize, SMEM_BYTES);

    prep_Wg_kernel<<<32, 128>>>(Wg);
    gate_kernel<<<MBLKS, 512>>>((const float4*)x, bg, We);
    moe_mma_kernel<<<(BATCH / BM) * (NCOL / BN), NTHREADS, SMEM_BYTES>>>(be, out);
}

// round 15
// speedup vs baseline: 1.5757x; 1.5757x over previous
#include <cuda_runtime.h>
#include <cuda_fp16.h>
#include <cstdint>
#include <cstddef>

// ============================================================================
// Problem constants
// ============================================================================
static constexpr int BATCH  = 16384;
static constexpr int IN_DIM = 512;
static constexpr int UNITS  = 256;
static constexpr int NEXP   = 8;
static constexpr int NTASK  = 4;
static constexpr int NCOL   = UNITS * NEXP;   // 2048, n = u*8+e
static constexpr int GCOL   = NEXP * NTASK;   // 32,   g = e*4+t

// Fragment-block geometry (mma.m16n8k16.f16)
static constexpr int MBLKS  = BATCH / 16;     // 1024
static constexpr int KB16   = IN_DIM / 16;    // 32  (A k-blocks)
static constexpr int KB32   = IN_DIM / 32;    // 16  (B k-block pairs)
static constexpr int NBLKS  = NCOL / 8;       // 256
static constexpr int GNBLKS = GCOL / 8;       // 4

// Tiling: 4 warps of 64x64
static constexpr int BM     = 128;            // 8 m_blks -> 2048 CTAs
static constexpr int BN     = 128;            // 16 n_blks
static constexpr int KC     = 32;             // 2 k16 / 1 k32 per stage
static constexpr int KSTEPS = IN_DIM / KC;    // 16
static constexpr int STAGES = 3;
static constexpr int NTHREADS = 128;          // 4 warps, 2(m) x 2(n), 64x64 tiles

// Shared memory (uint4 units): stage = A(8*2*32) + B(16*1*32) = 1024 u4 = 16KB
static constexpr int A_STAGE_U4 = 8 * 2 * 32;     // 512
static constexpr int B_STAGE_U4 = 16 * 32;        // 512
static constexpr int STAGE_U4   = A_STAGE_U4 + B_STAGE_U4;  // 1024
static constexpr int HDR_U4     = 32;             // be slice (128 floats)
static constexpr int SMEM_U4    = HDR_U4 + STAGES * STAGE_U4;
static constexpr int SMEM_BYTES = SMEM_U4 * 16;   // 49664 (x2 CTA = 97 KB)
static constexpr int C_LD       = BN + 4;         // 132 (staging 128*132*4 = 67.6 KB)

// ============================================================================
// Device scratch (no allocations allowed)
// ============================================================================
__device__ float g_gates[BATCH * GCOL];                  // softmaxed gates
__device__ uint4 g_xA [(size_t)MBLKS * KB16 * 32];       // A frags fp16 (16 MB)
__device__ uint4 g_WeB[(size_t)NBLKS * KB32 * 32];       // We B frags  ( 2 MB)
__device__ uint4 g_WgB[(size_t)GNBLKS * KB32 * 32];      // Wg B frags  (32 KB)

// ============================================================================
// Helpers
// ============================================================================
__device__ __forceinline__ uint32_t smem_u32(const void* p) {
    uint32_t a;
    asm("{ .reg .u64 t; cvta.to.shared.u64 t, %1; cvt.u32.u64 %0, t; }" : "=r"(a) : "l"(p));
    return a;
}
__device__ __forceinline__ uint32_t pack_h2(float lo, float hi) {
    __half2 h = __floats2half2_rn(lo, hi);   // .x = lo (k even), .y = hi (k odd)
    return *(uint32_t*)&h;
}
__device__ __forceinline__ void cp_async16(uint32_t dst, const void* src) {
    asm volatile("cp.async.cg.shared.global [%0], [%1], 16;\n" :: "r"(dst), "l"(src));
}
#define CP_COMMIT()       asm volatile("cp.async.commit_group;\n" ::: "memory")
#define CP_WAIT_GROUP_1() asm volatile("cp.async.wait_group 1;\n" ::: "memory")

// D += A(16x16) * B(16x8), fp16 operands, f32 accum
__device__ __forceinline__ void mma_f16(float* c, const uint4& a, uint32_t b0, uint32_t b1) {
    asm volatile(
        "mma.sync.aligned.m16n8k16.row.col.f32.f16.f16.f32 "
        "{%0,%1,%2,%3}, {%4,%5,%6,%7}, {%8,%9}, {%0,%1,%2,%3};"
        : "+f"(c[0]), "+f"(c[1]), "+f"(c[2]), "+f"(c[3])
        : "r"(a.x), "r"(a.y), "r"(a.z), "r"(a.w), "r"(b0), "r"(b1));
}

// ============================================================================
// prep Wg: pack Wg into fp16 B-fragment order (2048 u4 slots)
// ============================================================================
__global__ void __launch_bounds__(128)
prep_Wg_kernel(const float* __restrict__ Wg) {
    int slot = blockIdx.x * 128 + threadIdx.x;   // 16 blocks x 128 = 2048
    int gn   = slot >> 9;
    int rem  = slot & 511;
    int kb32 = rem >> 5;
    int ln   = rem & 31;
    int g2 = ln >> 2, t2 = ln & 3;
    int n  = gn * 8 + g2;
    int kb = kb32 * 32;
    uint4 v;
    v.x = pack_h2(__ldg(Wg + (size_t)(kb + 2*t2)      * GCOL + n),
                  __ldg(Wg + (size_t)(kb + 2*t2 + 1)  * GCOL + n));
    v.y = pack_h2(__ldg(Wg + (size_t)(kb + 2*t2 + 8)  * GCOL + n),
                  __ldg(Wg + (size_t)(kb + 2*t2 + 9)  * GCOL + n));
    v.z = pack_h2(__ldg(Wg + (size_t)(kb + 2*t2 + 16) * GCOL + n),
                  __ldg(Wg + (size_t)(kb + 2*t2 + 17) * GCOL + n));
    v.w = pack_h2(__ldg(Wg + (size_t)(kb + 2*t2 + 24) * GCOL + n),
                  __ldg(Wg + (size_t)(kb + 2*t2 + 25) * GCOL + n));
    g_WgB[slot] = v;
}

// ============================================================================
// Gate kernel: x fp16 A-fragment pack + tensor-core gate logits + softmax.
// Also packs a uniform 128-slot slice of We B-fragments per block
// (1024 blocks x 128 = 131072 slots = full g_WeB).
// ============================================================================
static constexpr int XS_LD = IN_DIM + 4;   // 516

__global__ void __launch_bounds__(512)
gate_kernel(const float4* __restrict__ x4, const float* __restrict__ bg,
            const float* __restrict__ We) {
    __shared__ float xs[16][XS_LD];        // 33 KB
    __shared__ float ls[16][GCOL];         //  2 KB
    const int tid  = threadIdx.x;
    const int wid  = tid >> 5;
    const int lane = tid & 31;
    const int gr   = lane >> 2, tig = lane & 3;
    const int blk  = blockIdx.x;           // m_blk
    const int b0   = blk * 16;

    // Uniform We B-fragment pack slice: 128 slots for this block.
    if (tid < 128) {
        int s    = blk * 128 + tid;        // flat g_WeB index
        int rem  = s & 511;
        int kb32 = rem >> 5;
        int ln   = rem & 31;
        int g2 = ln >> 2, t2 = ln & 3;
        int n  = (s >> 9) * 8 + g2;
        int kb = kb32 * 32;
        uint4 v;
        v.x = pack_h2(__ldg(We + (size_t)(kb + 2*t2)      * NCOL + n),
                      __ldg(We + (size_t)(kb + 2*t2 + 1)  * NCOL + n));
        v.y = pack_h2(__ldg(We + (size_t)(kb + 2*t2 + 8)  * NCOL + n),
                      __ldg(We + (size_t)(kb + 2*t2 + 9)  * NCOL + n));
        v.z = pack_h2(__ldg(We + (size_t)(kb + 2*t2 + 16) * NCOL + n),
                      __ldg(We + (size_t)(kb + 2*t2 + 17) * NCOL + n));
        v.w = pack_h2(__ldg(We + (size_t)(kb + 2*t2 + 24) * NCOL + n),
                      __ldg(We + (size_t)(kb + 2*t2 + 25) * NCOL + n));
        g_WeB[s] = v;
    }

    // load x tile into smem (fp32; fp16 rounding happens at pack)
    #pragma unroll
    for (int i = 0; i < 4; i++) {
        int idx = tid + i * 512;
        int rr = idx >> 7, c = idx & 127;
        float4 v = x4[(size_t)(b0 + rr) * (IN_DIM / 4) + c];
        *(float4*)&xs[rr][c * 4] = v;
    }
    __syncthreads();

    // write fp16 A fragments to gmem (1024 slots = 32 k16 x 32 lanes)
    #pragma unroll
    for (int i = 0; i < 2; i++) {
        int slot = tid + i * 512;
        int k16  = slot >> 5;
        int ln   = slot & 31;
        int g2 = ln >> 2, t2 = ln & 3;
        int kc = k16 * 16;
        uint4 v;
        v.x = pack_h2(xs[g2][kc + 2*t2],       xs[g2][kc + 2*t2 + 1]);
        v.y = pack_h2(xs[g2 + 8][kc + 2*t2],   xs[g2 + 8][kc + 2*t2 + 1]);
        v.z = pack_h2(xs[g2][kc + 2*t2 + 8],   xs[g2][kc + 2*t2 + 9]);
        v.w = pack_h2(xs[g2 + 8][kc + 2*t2 + 8], xs[g2 + 8][kc + 2*t2 + 9]);
        g_xA[((size_t)blk * KB16 + k16) * 32 + ln] = v;
    }
    __syncthreads();   // own-block global writes now visible to this block

    // gate logits via fp16 tensor cores: warps 0..3, one gate n-blk each
    if (wid < GNBLKS) {
        float a[4] = {0.f, 0.f, 0.f, 0.f};
        const uint4* WgB = g_WgB + (size_t)wid * KB32 * 32;
        const uint4* xA  = g_xA + (size_t)blk * KB16 * 32;
        #pragma unroll 4
        for (int kb32 = 0; kb32 < KB32; kb32++) {
            uint4 Bv  = WgB[kb32 * 32 + lane];
            uint4 Av0 = xA[(kb32 * 2) * 32 + lane];
            uint4 Av1 = xA[(kb32 * 2 + 1) * 32 + lane];
            mma_f16(a, Av0, Bv.x, Bv.y);
            mma_f16(a, Av1, Bv.z, Bv.w);
        }
        ls[gr][wid * 8 + 2 * tig]         = a[0];
        ls[gr][wid * 8 + 2 * tig + 1]     = a[1];
        ls[gr + 8][wid * 8 + 2 * tig]     = a[2];
        ls[gr + 8][wid * 8 + 2 * tig + 1] = a[3];
    }
    __syncthreads();

    // softmax over experts, per (row, task)
    if (tid < 64) {
        const int rr = tid >> 2, t = tid & 3;
        float v[NEXP], m = -3.4e38f;
        #pragma unroll
        for (int e = 0; e < NEXP; e++) {
            v[e] = ls[rr][e * 4 + t] + bg[e * 4 + t];
            m = fmaxf(m, v[e]);
        }
        float den = 0.f;
        #pragma unroll
        for (int e = 0; e < NEXP; e++) { v[e] = expf(v[e] - m); den += v[e]; }
        const float inv = 1.f / den;
        #pragma unroll
        for (int e = 0; e < NEXP; e++)
            g_gates[(size_t)(b0 + rr) * GCOL + e * 4 + t] = v[e] * inv;
    }
}

// ============================================================================
// Main kernel: mma.m16n8k16 fp16, 64x64 warp tiles — half the MMA count
// ============================================================================
__global__ void __launch_bounds__(NTHREADS, 2)
moe_mma_kernel(const float* __restrict__ be, float* __restrict__ out) {
    extern __shared__ uint4 smem4[];
    float* sbe    = (float*)smem4;
    uint4* stage0 = smem4 + HDR_U4;

    const int tid  = threadIdx.x;
    const int wid  = tid >> 5;
    const int lane = tid & 31;
    const int gr   = lane >> 2, tig = lane & 3;
    const int warp_m = wid >> 1;        // 0..1 -> rows warp_m*64
    const int warp_n = wid & 1;         // 0..1 -> cols warp_n*64

    const int n_tile = blockIdx.x & 15;
    const int b_tile = blockIdx.x >> 4;
    const int b0  = b_tile * BM;
    const int mb0 = b_tile * 8;         // global m_blk base
    const int nb0 = n_tile * 16;        // global n_blk base

    if (tid < BN) sbe[tid] = be[n_tile * BN + tid];

    float acc[4][8][4];                 // [mi][ni][frag] = 128 regs
    #pragma unroll
    for (int mi = 0; mi < 4; mi++)
        #pragma unroll
        for (int ni = 0; ni < 8; ni++)
            #pragma unroll
            for (int q = 0; q < 4; q++) acc[mi][ni][q] = 0.f;

    auto load_stage = [&](int slot, int kt) {
        uint4* As = stage0 + slot * STAGE_U4;
        uint4* Bs = As + A_STAGE_U4;
        const uint32_t aB = smem_u32(As);
        const uint32_t bB = smem_u32(Bs);
        // A: 512 chunks; c = (mb_l*2 + k16_l)*32 + lane -> 4 per thread
        #pragma unroll
        for (int i = 0; i < 4; i++) {
            int c = tid + i * 128;
            int mb = c >> 6, rem = c & 63;
            size_t g = ((size_t)(mb0 + mb) * KB16 + (kt * 2 + (rem >> 5))) * 32 + (rem & 31);
            cp_async16(aB + (uint32_t)c * 16, g_xA + g);
        }
        // B: 512 chunks; c = nb_l*32 + lane -> 4 per thread
        #pragma unroll
        for (int i = 0; i < 4; i++) {
            int c = tid + i * 128;
            int nb = c >> 5, ln = c & 31;
            size_t g = ((size_t)(nb0 + nb) * KB32 + kt) * 32 + ln;
            cp_async16(bB + (uint32_t)c * 16, g_WeB + g);
        }
    };

    auto compute_stage = [&](int slot) {
        const uint4* As = stage0 + slot * STAGE_U4;
        const uint4* Bs = As + A_STAGE_U4;
        uint4 Bv[8];
        #pragma unroll
        for (int ni = 0; ni < 8; ni++)
            Bv[ni] = Bs[(warp_n * 8 + ni) * 32 + lane];
        #pragma unroll
        for (int h = 0; h < 2; h++) {
            uint4 Av[4];
            #pragma unroll
            for (int mi = 0; mi < 4; mi++)
                Av[mi] = As[((warp_m * 4 + mi) * 2 + h) * 32 + lane];
            #pragma unroll
            for (int mi = 0; mi < 4; mi++)
                #pragma unroll
                for (int ni = 0; ni < 8; ni++) {
                    if (h == 0) mma_f16(acc[mi][ni], Av[mi], Bv[ni].x, Bv[ni].y);
                    else        mma_f16(acc[mi][ni], Av[mi], Bv[ni].z, Bv[ni].w);
                }
        }
    };

    // Prologue: fill 2 of 3 stages
    load_stage(0, 0); CP_COMMIT();
    load_stage(1, 1); CP_COMMIT();

    // Main loop
    for (int kt = 0; kt < KSTEPS; kt++) {
        CP_WAIT_GROUP_1();
        __syncthreads();
        const int next = kt + 2;
        if (next < KSTEPS) load_stage(next % STAGES, next);
        CP_COMMIT();
        compute_stage(kt % STAGES);
    }

    // ------------------------------------------------------------------
    // Epilogue: stage C through smem, then bias+ReLU+gate combine
    // ------------------------------------------------------------------
    __syncthreads();
    float* Cs = (float*)stage0;   // 128 x 132 floats = 67.6 KB... (> 48KB stages!)
    // NOTE: C staging needs 67.6KB but stage region is 48KB + hdr; total smem is
    // 49.6KB. Stage C in two half-tiles of 64 rows (33.8KB each) instead.
    #pragma unroll
    for (int halfm = 0; halfm < 2; halfm++) {
        // warps with warp_m == halfm write their 64 rows
        if (warp_m == halfm) {
            #pragma unroll
            for (int mi = 0; mi < 4; mi++) {
                #pragma unroll
                for (int ni = 0; ni < 8; ni++) {
                    int row = mi * 16 + gr;            // 0..63 within half
                    int col = warp_n * 64 + ni * 8 + 2 * tig;
                    *(float2*)&Cs[row * C_LD + col]       = make_float2(acc[mi][ni][0], acc[mi][ni][1]);
                    *(float2*)&Cs[(row + 8) * C_LD + col] = make_float2(acc[mi][ni][2], acc[mi][ni][3]);
                }
            }
        }
        __syncthreads();

        // all 128 threads process one row each of this 64-row half (2 threads/row)
        {
            const int r  = tid >> 1;          // 0..63
            const int hh = tid & 1;           // column half (8 units)
            const int b  = b0 + halfm * 64 + r;

            float gate[GCOL];
            const float4* gp = (const float4*)(g_gates + (size_t)b * GCOL);
            #pragma unroll
            for (int q = 0; q < 8; q++) ((float4*)gate)[q] = gp[q];

            float accu[8][NTASK];
            #pragma unroll
            for (int u = 0; u < 8; u++)
                #pragma unroll
                for (int t = 0; t < NTASK; t++) accu[u][t] = 0.f;

            #pragma unroll
            for (int u = 0; u < 8; u++) {
                const int nl = (hh * 8 + u) * 8;
                #pragma unroll
                for (int e = 0; e < NEXP; e++) {
                    float v = Cs[r * C_LD + nl + e] + sbe[nl + e];
                    v = fmaxf(v, 0.f);
                    #pragma unroll
                    for (int t = 0; t < NTASK; t++) accu[u][t] += v * gate[e * 4 + t];
                }
            }

            float* ob = out + (size_t)b * UNITS + n_tile * 16 + hh * 8;
            #pragma unroll
            for (int t = 0; t < NTASK; t++) {
                float4 o0 = make_float4(accu[0][t], accu[1][t], accu[2][t], accu[3][t]);
                float4 o1 = make_float4(accu[4][t], accu[5][t], accu[6][t], accu[7][t]);
                *(float4*)(ob + (size_t)t * BATCH * UNITS)     = o0;
                *(float4*)(ob + (size_t)t * BATCH * UNITS + 4) = o1;
            }
        }
        __syncthreads();
    }
}

// ============================================================================
// Launch
// ============================================================================
extern "C" void kernel_launch(void* const* d_in, const int* in_sizes, int n_in,
                              void* d_out, int out_size) {
    const float* x  = (const float*)d_in[0];
    const float* We = (const float*)d_in[1];
    const float* be = (const float*)d_in[2];
    const float* Wg = (const float*)d_in[3];
    const float* bg = (const float*)d_in[4];
    float* out = (float*)d_out;

    cudaFuncSetAttribute(moe_mma_kernel, cudaFuncAttributeMaxDynamicSharedMemorySize, SMEM_BYTES);

    prep_Wg_kernel<<<16, 128>>>(Wg);
    gate_kernel<<<MBLKS, 512>>>((const float4*)x, bg, We);
    moe_mma_kernel<<<(BATCH / BM) * (NCOL / BN), NTHREADS, SMEM_BYTES>>>(be, out);
}